// round 3
// baseline (speedup 1.0000x reference)
#include <cuda_runtime.h>
#include <cuda_bf16.h>

#define BIG 1e9f
#define FULLMASK 0xFFFFFFFFu

// Two images per warp: lanes 0-15 -> image 2w, lanes 16-31 -> image 2w+1.
// Each lane owns 4 consecutive columns (float4 per row). Min-plus row scan:
// in-thread tree combine of 4 cols -> 4-step segmented (width=16) warp scan
// -> reconstruction from saved partial prefixes.
__global__ void __launch_bounds__(128, 16) dp_shortest_path_kernel(
    const float* __restrict__ img, float* __restrict__ out, int B)
{
    const int warp_global = (blockIdx.x * blockDim.x + threadIdx.x) >> 5;
    const int lane = threadIdx.x & 31;
    const int sl = lane & 15;                       // sub-lane within 16-wide segment
    if (warp_global * 2 >= B) return;               // whole warp exits together

    int img_idx = warp_global * 2 + (lane >> 4);
    const bool valid = (img_idx < B);
    if (!valid) img_idx = B - 1;                    // keep all lanes in shfl

    const float4* row = reinterpret_cast<const float4*>(img + (size_t)img_idx * 4096) + sl;

    float4 cur = __ldg(row);
    float4 nxt = __ldg(row + 16);

    float a0, a1, a2, a3, c0, c1, c2, c3;
    float v0, v1, v2, v3;

    // ---- Row 0: c finite only at col 0; right-edge weights fold in via scan
    {
        float xl = __shfl_up_sync(FULLMASK, cur.w, 1, 16);  // img[0][4sl-1]
        a0 = (sl == 0) ? BIG : 0.5f * (xl + cur.x);
        a1 = 0.5f * (cur.x + cur.y);
        a2 = 0.5f * (cur.y + cur.z);
        a3 = 0.5f * (cur.z + cur.w);
        c0 = (sl == 0) ? 0.0f : BIG;
        c1 = BIG; c2 = BIG; c3 = BIG;
    }

    float4 prev = cur;
    float pd0, pd1, pd2, pd3;

    #pragma unroll 1
    for (int i = 0; i < 64; i++) {
        if (i > 0) {
            cur = nxt;
            if (i < 63) nxt = __ldg(row + (i + 1) * 16);

            float pxl = __shfl_up_sync(FULLMASK, prev.w, 1, 16); // img[i-1][4sl-1]
            float xl  = __shfl_up_sync(FULLMASK, cur.w,  1, 16); // img[i  ][4sl-1]
            float pdl = __shfl_up_sync(FULLMASK, pd3,    1, 16); // d[i-1][4sl-1]

            // down-edge candidates
            c0 = pd0 + 0.5f * (prev.x + cur.x);
            c1 = pd1 + 0.5f * (prev.y + cur.y);
            c2 = pd2 + 0.5f * (prev.z + cur.z);
            c3 = pd3 + 0.5f * (prev.w + cur.w);
            // diag-edge candidates
            float dg0 = pdl + 0.5f * (pxl + cur.x);
            if (sl > 0) c0 = fminf(c0, dg0);
            c1 = fminf(c1, pd0 + 0.5f * (prev.x + cur.y));
            c2 = fminf(c2, pd1 + 0.5f * (prev.y + cur.z));
            c3 = fminf(c3, pd2 + 0.5f * (prev.z + cur.w));
            // right-edge weights
            a0 = (sl == 0) ? BIG : 0.5f * (xl + cur.x);
            a1 = 0.5f * (cur.x + cur.y);
            a2 = 0.5f * (cur.y + cur.z);
            a3 = 0.5f * (cur.z + cur.w);
        }

        // ---- min-plus scan of the 64-wide row ----
        // in-thread tree combine (keep partials for reconstruction)
        float A01  = a0 + a1;
        float C01  = fminf(c1, c0 + a1);
        float A23  = a2 + a3;
        float C23  = fminf(c3, c2 + a3);
        float A012 = A01 + a2;
        float C012 = fminf(c2, C01 + a2);
        float A    = A01 + A23;
        float C    = fminf(C23, C01 + A23);

        // 4-step segmented inclusive scan over 16 lanes
        #pragma unroll
        for (int off = 1; off < 16; off <<= 1) {
            float Ap = __shfl_up_sync(FULLMASK, A, off, 16);
            float Cp = __shfl_up_sync(FULLMASK, C, off, 16);
            if (sl >= off) {
                C = fminf(C, Cp + A);
                A = Ap + A;
            }
        }
        float Cex = __shfl_up_sync(FULLMASK, C, 1, 16);  // v[4sl-1]; garbage at sl=0 but a0=BIG guards

        // reconstruct per-lane outputs (one dependent level after Cex)
        v0 = fminf(c0,   Cex + a0);
        v1 = fminf(C01,  Cex + A01);
        v2 = fminf(C012, Cex + A012);
        v3 = C;

        pd0 = v0; pd1 = v1; pd2 = v2; pd3 = v3;
        prev = cur;
    }

    if (sl == 15 && valid) out[img_idx] = pd3;   // d[63][63]
}

extern "C" void kernel_launch(void* const* d_in, const int* in_sizes, int n_in,
                              void* d_out, int out_size) {
    const float* img = (const float*)d_in[0];
    float* out = (float*)d_out;
    int B = in_sizes[0] / (64 * 64);
    int warps = (B + 1) / 2;                    // 2 images per warp
    int threads = 128;                          // 4 warps per block
    int blocks = (warps * 32 + threads - 1) / threads;
    dp_shortest_path_kernel<<<blocks, threads>>>(img, out, B);
}